// round 9
// baseline (speedup 1.0000x reference)
#include <cuda_runtime.h>
#include <cstdint>

#define VOCAB  50257
#define BATCH  4096
#define NBLK   592          // 148 SMs x 4 CTAs -> one persistent wave
#define NTHR   256
#define CHUNKS 4
#define NTASK  (BATCH * CHUNKS)   // 16384
#define QCOLS  12568              // cols per chunk (last chunk = 12553)

// Scratch (no device mallocs).
__device__ __align__(16) float g_chunk[NTASK];
__device__ float g_cta_sum[NBLK];
__device__ unsigned int g_sync1 = 0;  // monotonic ticket counter (never reset)
__device__ unsigned int g_done  = 0;  // self-resetting each launch

__global__ __launch_bounds__(NTHR, 4) void ce_fused_kernel(
    const float* __restrict__ pred,
    const int* __restrict__ y,        // JAX x64-disabled => int32 labels
    float* __restrict__ out)
{
    const int tid = threadIdx.x;
    const int T = NTHR;
    const int wid = tid >> 5;
    const int lid = tid & 31;
    __shared__ float sm[8];

    // ---- Phase 1: chunk exp-sums; lockstep warps, one chunk at a time ----
    for (int t = blockIdx.x; t < NTASK; t += NBLK) {
        const int row  = t >> 2;
        const int c    = t & 3;
        const int col0 = c * QCOLS;
        const int ncols = (c == 3) ? (VOCAB - 3 * QCOLS) : QCOLS;
        const float* __restrict__ p = pred + (size_t)row * VOCAB + col0;

        // Chunk base misalignment (floats) rel. 16B; prologue to align.
        const int mis = (int)(((uintptr_t)p & 15u) >> 2);
        const int pro = (4 - mis) & 3;

        float s0 = 0.f, s1 = 0.f, s2 = 0.f, s3 = 0.f;

        if (tid < pro) s0 += __expf(p[tid]);

        const float4* __restrict__ p4 = (const float4*)(p + pro);
        const int n4 = (ncols - pro) >> 2;

        // 4 front-batched streaming LDG.128, then 16 EX2.
        int i = tid;
        for (; i + 3 * T < n4; i += 4 * T) {
            float4 v[4];
            #pragma unroll
            for (int u = 0; u < 4; u++)
                v[u] = __ldcs(&p4[i + u * T]);
            #pragma unroll
            for (int u = 0; u < 4; u++) {
                s0 += __expf(v[u].x);
                s1 += __expf(v[u].y);
                s2 += __expf(v[u].z);
                s3 += __expf(v[u].w);
            }
        }
        for (; i < n4; i += T) {
            float4 v = __ldcs(&p4[i]);
            s0 += __expf(v.x);
            s1 += __expf(v.y);
            s2 += __expf(v.z);
            s3 += __expf(v.w);
        }

        const int done = pro + (n4 << 2);
        const int tail = ncols - done;
        if (tid < tail) s1 += __expf(p[done + tid]);

        float s = (s0 + s1) + (s2 + s3);

        // Block reduction (fixed order -> deterministic).
        #pragma unroll
        for (int o = 16; o > 0; o >>= 1)
            s += __shfl_xor_sync(0xffffffffu, s, o);
        if (lid == 0) sm[wid] = s;
        __syncthreads();
        if (tid == 0)
            g_chunk[t] = (sm[0] + sm[1]) + (sm[2] + sm[3])
                       + ((sm[4] + sm[5]) + (sm[6] + sm[7]));
        __syncthreads();   // sm reuse + re-lockstep warps
    }

    // ---- Grid sync: monotonic ticket (graph-replay safe, no reset) ----
    if (tid == 0) {
        __threadfence();
        unsigned int ticket = atomicAdd(&g_sync1, 1u);
        unsigned int target = ticket - (ticket % NBLK) + NBLK;  // end of this launch's round
        while ((int)(*(volatile unsigned int*)&g_sync1 - target) < 0) { }
        __threadfence();
    }
    __syncthreads();

    // ---- Phase 2: warp 0 finalizes this CTA's rows (lanes parallel) ----
    if (wid == 0) {
        float acc = 0.f;
        for (int j = lid; ; j += 32) {
            const int r = blockIdx.x + j * NBLK;
            if (r >= BATCH) break;
            const float4 cs = *(const float4*)&g_chunk[4 * r];
            const float v = (cs.x + cs.y) + (cs.z + cs.w);
            const int tgt = y[r];
            acc += __logf(v) - pred[(size_t)r * VOCAB + tgt];
        }
        #pragma unroll
        for (int o = 16; o > 0; o >>= 1)
            acc += __shfl_xor_sync(0xffffffffu, acc, o);
        if (lid == 0) g_cta_sum[blockIdx.x] = acc;
    }
    __syncthreads();

    // ---- Completion: last CTA reduces 592 per-CTA sums ----
    __shared__ bool is_last;
    if (tid == 0) {
        __threadfence();
        unsigned int prev = atomicAdd(&g_done, 1u);
        is_last = (prev == (unsigned)(NBLK - 1));
    }
    __syncthreads();

    if (is_last) {
        float r = 0.f;
        for (int i = tid; i < NBLK; i += NTHR)
            r += g_cta_sum[i];

        #pragma unroll
        for (int o = 16; o > 0; o >>= 1)
            r += __shfl_xor_sync(0xffffffffu, r, o);
        if (lid == 0) sm[wid] = r;
        __syncthreads();
        if (tid == 0) {
            float tot = (sm[0] + sm[1]) + (sm[2] + sm[3])
                      + ((sm[4] + sm[5]) + (sm[6] + sm[7]));
            out[0] = tot * (1.0f / BATCH);
            g_done = 0;   // reset for next launch / graph replay
        }
    }
}

extern "C" void kernel_launch(void* const* d_in, const int* in_sizes, int n_in,
                              void* d_out, int out_size)
{
    const float* pred = (const float*)d_in[0];
    const int* y = (const int*)d_in[1];
    float* out = (float*)d_out;

    ce_fused_kernel<<<NBLK, NTHR>>>(pred, y, out);
}

// round 10
// speedup vs baseline: 1.0344x; 1.0344x over previous
#include <cuda_runtime.h>
#include <cstdint>

#define VOCAB   50257
#define BATCH   4096
#define NBLK    592        // 148 SMs x 4 CTAs -> one persistent wave
#define NTHR    256
#define AROWS   3552       // 6 whole rows per CTA (NBLK*6), perfectly balanced
#define BROWS   (BATCH - AROWS)    // 544 remainder rows
#define CHUNKS  4
#define NTASK   (BROWS * CHUNKS)   // 2176 quarter-row chunks
#define QCOLS   12568              // floats per chunk (last chunk = 12553)

// Scratch (no device mallocs).
__device__ __align__(16) float g_chunk[NTASK];
__device__ float g_cta_sum[NBLK];
__device__ unsigned int g_done = 0;   // self-resetting each launch

__global__ __launch_bounds__(NTHR, 4) void ce_fused_kernel(
    const float* __restrict__ pred,
    const int* __restrict__ y,        // JAX x64-disabled => int32 labels
    float* __restrict__ out)
{
    const int tid = threadIdx.x;
    const int T = NTHR;
    const int wid = tid >> 5;
    const int lid = tid & 31;
    __shared__ float sm[8];

    float cta_loss = 0.f;   // meaningful in tid 0 only

    // ================= Phase A: 6 whole rows per CTA (balanced) =============
    #pragma unroll 1
    for (int j = 0; j < 6; j++) {
        const int row = blockIdx.x + j * NBLK;
        const float* __restrict__ p = pred + (size_t)row * VOCAB;

        const int mis = (int)(((uintptr_t)p & 15u) >> 2);
        const int pro = (4 - mis) & 3;

        float s0 = 0.f, s1 = 0.f, s2 = 0.f, s3 = 0.f;
        if (tid < pro) s0 += __expf(p[tid]);

        const float4* __restrict__ p4 = (const float4*)(p + pro);
        const int n4 = (VOCAB - pro) >> 2;

        // 8 front-batched streaming LDG.128, then 32 EX2.
        int i = tid;
        for (; i + 7 * T < n4; i += 8 * T) {
            float4 v[8];
            #pragma unroll
            for (int u = 0; u < 8; u++)
                v[u] = __ldcs(&p4[i + u * T]);
            #pragma unroll
            for (int u = 0; u < 8; u++) {
                s0 += __expf(v[u].x);
                s1 += __expf(v[u].y);
                s2 += __expf(v[u].z);
                s3 += __expf(v[u].w);
            }
        }
        for (; i < n4; i += T) {
            float4 v = __ldcs(&p4[i]);
            s0 += __expf(v.x);
            s1 += __expf(v.y);
            s2 += __expf(v.z);
            s3 += __expf(v.w);
        }

        const int done = pro + (n4 << 2);
        const int tail = VOCAB - done;
        if (tid < tail) s1 += __expf(p[done + tid]);

        float s = (s0 + s1) + (s2 + s3);
        #pragma unroll
        for (int o = 16; o > 0; o >>= 1)
            s += __shfl_xor_sync(0xffffffffu, s, o);
        if (lid == 0) sm[wid] = s;
        __syncthreads();
        if (tid == 0) {
            float v = (sm[0] + sm[1]) + (sm[2] + sm[3])
                    + ((sm[4] + sm[5]) + (sm[6] + sm[7]));
            const int tgt = y[row];
            cta_loss += __logf(v) - p[tgt];
        }
        __syncthreads();
    }

    // ============ Phase B: quarter-row chunks of the 544 remainder ==========
    for (int q = blockIdx.x; q < NTASK; q += NBLK) {
        const int row  = AROWS + (q >> 2);
        const int c    = q & 3;
        const int col0 = c * QCOLS;
        const int ncols = (c == 3) ? (VOCAB - 3 * QCOLS) : QCOLS;
        const float* __restrict__ p = pred + (size_t)row * VOCAB + col0;

        const int mis = (int)(((uintptr_t)p & 15u) >> 2);
        const int pro = (4 - mis) & 3;

        float s0 = 0.f, s1 = 0.f, s2 = 0.f, s3 = 0.f;
        if (tid < pro) s0 += __expf(p[tid]);

        const float4* __restrict__ p4 = (const float4*)(p + pro);
        const int n4 = (ncols - pro) >> 2;

        int i = tid;
        for (; i + 7 * T < n4; i += 8 * T) {
            float4 v[8];
            #pragma unroll
            for (int u = 0; u < 8; u++)
                v[u] = __ldcs(&p4[i + u * T]);
            #pragma unroll
            for (int u = 0; u < 8; u++) {
                s0 += __expf(v[u].x);
                s1 += __expf(v[u].y);
                s2 += __expf(v[u].z);
                s3 += __expf(v[u].w);
            }
        }
        for (; i < n4; i += T) {
            float4 v = __ldcs(&p4[i]);
            s0 += __expf(v.x);
            s1 += __expf(v.y);
            s2 += __expf(v.z);
            s3 += __expf(v.w);
        }

        const int done = pro + (n4 << 2);
        const int tail = ncols - done;
        if (tid < tail) s1 += __expf(p[done + tid]);

        float s = (s0 + s1) + (s2 + s3);
        #pragma unroll
        for (int o = 16; o > 0; o >>= 1)
            s += __shfl_xor_sync(0xffffffffu, s, o);
        if (lid == 0) sm[wid] = s;
        __syncthreads();
        if (tid == 0)
            g_chunk[q] = (sm[0] + sm[1]) + (sm[2] + sm[3])
                       + ((sm[4] + sm[5]) + (sm[6] + sm[7]));
        __syncthreads();
    }

    // ================= Completion: last CTA finalizes =======================
    __shared__ bool is_last;
    if (tid == 0) {
        g_cta_sum[blockIdx.x] = cta_loss;
        __threadfence();
        unsigned int prev = atomicAdd(&g_done, 1u);
        is_last = (prev == (unsigned)(NBLK - 1));
    }
    __syncthreads();

    if (is_last) {
        // (1) 592 per-CTA sums (phase A rows).
        float r = 0.f;
        for (int i = tid; i < NBLK; i += NTHR)
            r += g_cta_sum[i];

        // (2) 544 remainder rows from chunk sums (L2-hot).
        for (int idx = tid; idx < BROWS; idx += NTHR) {
            const int row = AROWS + idx;
            const float4 cs = *(const float4*)&g_chunk[4 * idx];
            const float v = (cs.x + cs.y) + (cs.z + cs.w);
            const int tgt = y[row];
            r += __logf(v) - pred[(size_t)row * VOCAB + tgt];
        }

        #pragma unroll
        for (int o = 16; o > 0; o >>= 1)
            r += __shfl_xor_sync(0xffffffffu, r, o);
        if (lid == 0) sm[wid] = r;
        __syncthreads();
        if (tid == 0) {
            float tot = (sm[0] + sm[1]) + (sm[2] + sm[3])
                      + ((sm[4] + sm[5]) + (sm[6] + sm[7]));
            out[0] = tot * (1.0f / BATCH);
            g_done = 0;   // reset for next launch / graph replay
        }
    }
}

extern "C" void kernel_launch(void* const* d_in, const int* in_sizes, int n_in,
                              void* d_out, int out_size)
{
    const float* pred = (const float*)d_in[0];
    const int* y = (const int*)d_in[1];
    float* out = (float*)d_out;

    ce_fused_kernel<<<NBLK, NTHR>>>(pred, y, out);
}

// round 11
// speedup vs baseline: 1.0887x; 1.0524x over previous
#include <cuda_runtime.h>
#include <cstdint>

#define VOCAB 50257
#define BATCH 4096
#define NBLK  592   // 148 SMs x 4 CTAs -> exactly one persistent wave

// Scratch for per-row losses + completion counter (no device mallocs).
__device__ float g_row_loss[BATCH];
__device__ unsigned int g_done = 0;   // self-resetting each launch

__global__ __launch_bounds__(256, 4) void ce_fused_kernel(
    const float* __restrict__ pred,
    const int* __restrict__ y,       // JAX x64-disabled => int32 labels
    float* __restrict__ out)
{
    const int tid = threadIdx.x;
    const int T = 256;
    const int wid = tid >> 5;
    const int lid = tid & 31;
    __shared__ float sm[8];

    // Persistent loop: each CTA handles rows bid, bid+592, ...
    for (int row = blockIdx.x; row < BATCH; row += NBLK) {
        const float* __restrict__ p = pred + (size_t)row * VOCAB;

        // Row base misalignment (in floats) relative to 16B; prologue to align.
        const int mis = (int)(((uintptr_t)p & 15u) >> 2);
        const int pro = (4 - mis) & 3;

        float s0 = 0.f, s1 = 0.f, s2 = 0.f, s3 = 0.f;

        if (tid < pro) s0 += __expf(p[tid]);

        const float4* __restrict__ p4 = (const float4*)(p + pro);
        const int n4 = (VOCAB - pro) >> 2;

        // Main loop: 8 front-batched streaming LDG.128, then 32 EX2.
        int i = tid;
        for (; i + 7 * T < n4; i += 8 * T) {
            float4 v[8];
            #pragma unroll
            for (int u = 0; u < 8; u++)
                v[u] = __ldcs(&p4[i + u * T]);
            #pragma unroll
            for (int u = 0; u < 8; u++) {
                s0 += __expf(v[u].x);
                s1 += __expf(v[u].y);
                s2 += __expf(v[u].z);
                s3 += __expf(v[u].w);
            }
        }
        for (; i < n4; i += T) {
            float4 v = __ldcs(&p4[i]);
            s0 += __expf(v.x);
            s1 += __expf(v.y);
            s2 += __expf(v.z);
            s3 += __expf(v.w);
        }

        const int done = pro + (n4 << 2);
        const int tail = VOCAB - done;
        if (tid < tail) s1 += __expf(p[done + tid]);

        float s = (s0 + s1) + (s2 + s3);

        // Block reduction (fixed order -> deterministic).
        #pragma unroll
        for (int o = 16; o > 0; o >>= 1)
            s += __shfl_xor_sync(0xffffffffu, s, o);
        if (lid == 0) sm[wid] = s;
        __syncthreads();
        if (tid == 0) {
            float v = sm[0] + sm[1] + sm[2] + sm[3] + sm[4] + sm[5] + sm[6] + sm[7];
            const int t = y[row];
            // loss_row = log(sum_j exp(p_j)) - p[y]
            g_row_loss[row] = __logf(v) - p[t];
        }
        __syncthreads();   // protect sm[] reuse across row iterations
    }

    // CTA finished all its rows: signal, last CTA reduces.
    __shared__ bool is_last;
    if (tid == 0) {
        __threadfence();
        unsigned int prev = atomicAdd(&g_done, 1u);
        is_last = (prev == (unsigned)(NBLK - 1));
    }
    __syncthreads();

    if (is_last) {
        float r = 0.f;
        #pragma unroll
        for (int k = 0; k < BATCH / 256; k++)
            r += g_row_loss[tid + k * 256];

        #pragma unroll
        for (int o = 16; o > 0; o >>= 1)
            r += __shfl_xor_sync(0xffffffffu, r, o);
        if (lid == 0) sm[wid] = r;
        __syncthreads();
        if (tid == 0) {
            float tot = sm[0] + sm[1] + sm[2] + sm[3] + sm[4] + sm[5] + sm[6] + sm[7];
            out[0] = tot * (1.0f / BATCH);
            g_done = 0;   // reset for next launch / graph replay
        }
    }
}

extern "C" void kernel_launch(void* const* d_in, const int* in_sizes, int n_in,
                              void* d_out, int out_size)
{
    const float* pred = (const float*)d_in[0];
    const int* y = (const int*)d_in[1];
    float* out = (float*)d_out;

    ce_fused_kernel<<<NBLK, 256>>>(pred, y, out);
}

// round 12
// speedup vs baseline: 1.0926x; 1.0036x over previous
#include <cuda_runtime.h>
#include <cstdint>

#define VOCAB 50257
#define BATCH 4096
#define NBLK  592   // 148 SMs x 4 CTAs -> exactly one persistent wave

// Scratch for per-row losses + completion counter (no device mallocs).
__device__ float g_row_loss[BATCH];
__device__ unsigned int g_done = 0;   // self-resetting each launch

__global__ __launch_bounds__(256, 4) void ce_fused_kernel(
    const float* __restrict__ pred,
    const int* __restrict__ y,       // JAX x64-disabled => int32 labels
    float* __restrict__ out)
{
    const int tid = threadIdx.x;
    const int T = 256;
    const int wid = tid >> 5;
    const int lid = tid & 31;
    __shared__ float sm[2][8];       // double-buffered: one barrier per row

    // Persistent loop: each CTA handles rows bid, bid+592, ...
    int buf = 0;
    for (int row = blockIdx.x; row < BATCH; row += NBLK, buf ^= 1) {
        const float* __restrict__ p = pred + (size_t)row * VOCAB;

        // Row base misalignment (in floats) relative to 16B; prologue to align.
        const int mis = (int)(((uintptr_t)p & 15u) >> 2);
        const int pro = (4 - mis) & 3;

        float s0 = 0.f, s1 = 0.f, s2 = 0.f, s3 = 0.f;

        if (tid < pro) s0 += __expf(p[tid]);

        const float4* __restrict__ p4 = (const float4*)(p + pro);
        const int n4 = (VOCAB - pro) >> 2;

        // Main loop: 8 front-batched streaming LDG.128, then 32 EX2.
        int i = tid;
        for (; i + 7 * T < n4; i += 8 * T) {
            float4 v[8];
            #pragma unroll
            for (int u = 0; u < 8; u++)
                v[u] = __ldcs(&p4[i + u * T]);
            #pragma unroll
            for (int u = 0; u < 8; u++) {
                s0 += __expf(v[u].x);
                s1 += __expf(v[u].y);
                s2 += __expf(v[u].z);
                s3 += __expf(v[u].w);
            }
        }
        for (; i < n4; i += T) {
            float4 v = __ldcs(&p4[i]);
            s0 += __expf(v.x);
            s1 += __expf(v.y);
            s2 += __expf(v.z);
            s3 += __expf(v.w);
        }

        const int done = pro + (n4 << 2);
        const int tail = VOCAB - done;
        if (tid < tail) s1 += __expf(p[done + tid]);

        float s = (s0 + s1) + (s2 + s3);

        // Block reduction (fixed order -> deterministic).
        #pragma unroll
        for (int o = 16; o > 0; o >>= 1)
            s += __shfl_xor_sync(0xffffffffu, s, o);
        if (lid == 0) sm[buf][wid] = s;
        __syncthreads();   // single barrier: partials of THIS buffer visible.
        // Warps proceed straight into next row's loads; tid 0 finalizes this
        // row from buffer `buf` while the other buffer fills next iteration.
        if (tid == 0) {
            float v = sm[buf][0] + sm[buf][1] + sm[buf][2] + sm[buf][3]
                    + sm[buf][4] + sm[buf][5] + sm[buf][6] + sm[buf][7];
            const int t = y[row];
            // loss_row = log(sum_j exp(p_j)) - p[y]
            g_row_loss[row] = __logf(v) - p[t];
        }
    }

    // CTA finished all its rows: signal, last CTA reduces.
    __shared__ bool is_last;
    __syncthreads();   // ensure tid0's last g_row_loss store precedes fence
    if (tid == 0) {
        __threadfence();
        unsigned int prev = atomicAdd(&g_done, 1u);
        is_last = (prev == (unsigned)(NBLK - 1));
    }
    __syncthreads();

    if (is_last) {
        float r = 0.f;
        #pragma unroll
        for (int k = 0; k < BATCH / 256; k++)
            r += g_row_loss[tid + k * 256];

        #pragma unroll
        for (int o = 16; o > 0; o >>= 1)
            r += __shfl_xor_sync(0xffffffffu, r, o);
        if (lid == 0) sm[0][wid] = r;
        __syncthreads();
        if (tid == 0) {
            float tot = sm[0][0] + sm[0][1] + sm[0][2] + sm[0][3]
                      + sm[0][4] + sm[0][5] + sm[0][6] + sm[0][7];
            out[0] = tot * (1.0f / BATCH);
            g_done = 0;   // reset for next launch / graph replay
        }
    }
}

extern "C" void kernel_launch(void* const* d_in, const int* in_sizes, int n_in,
                              void* d_out, int out_size)
{
    const float* pred = (const float*)d_in[0];
    const int* y = (const int*)d_in[1];
    float* out = (float*)d_out;

    ce_fused_kernel<<<NBLK, 256>>>(pred, y, out);
}

// round 13
// speedup vs baseline: 1.0963x; 1.0034x over previous
#include <cuda_runtime.h>
#include <cstdint>

#define VOCAB 50257
#define BATCH 4096
#define NBLK  296   // 148 SMs x 2 CTAs -> one persistent wave, half the streams
#define NTHR  512

// Scratch for per-row losses + completion counter (no device mallocs).
__device__ float g_row_loss[BATCH];
__device__ unsigned int g_done = 0;   // self-resetting each launch

__global__ __launch_bounds__(NTHR, 2) void ce_fused_kernel(
    const float* __restrict__ pred,
    const int* __restrict__ y,       // JAX x64-disabled => int32 labels
    float* __restrict__ out)
{
    const int tid = threadIdx.x;
    const int T = NTHR;
    const int wid = tid >> 5;
    const int lid = tid & 31;
    __shared__ float sm[2][16];      // double-buffered, 16 warps

    // Persistent loop: each CTA handles rows bid, bid+296, ...
    int buf = 0;
    for (int row = blockIdx.x; row < BATCH; row += NBLK, buf ^= 1) {
        const float* __restrict__ p = pred + (size_t)row * VOCAB;

        // Row base misalignment (in floats) relative to 16B; prologue to align.
        const int mis = (int)(((uintptr_t)p & 15u) >> 2);
        const int pro = (4 - mis) & 3;

        float s0 = 0.f, s1 = 0.f, s2 = 0.f, s3 = 0.f;

        if (tid < pro) s0 += __expf(p[tid]);

        const float4* __restrict__ p4 = (const float4*)(p + pro);
        const int n4 = (VOCAB - pro) >> 2;

        // Main loop: 8 front-batched streaming LDG.128, then 32 EX2.
        int i = tid;
        for (; i + 7 * T < n4; i += 8 * T) {
            float4 v[8];
            #pragma unroll
            for (int u = 0; u < 8; u++)
                v[u] = __ldcs(&p4[i + u * T]);
            #pragma unroll
            for (int u = 0; u < 8; u++) {
                s0 += __expf(v[u].x);
                s1 += __expf(v[u].y);
                s2 += __expf(v[u].z);
                s3 += __expf(v[u].w);
            }
        }
        for (; i < n4; i += T) {
            float4 v = __ldcs(&p4[i]);
            s0 += __expf(v.x);
            s1 += __expf(v.y);
            s2 += __expf(v.z);
            s3 += __expf(v.w);
        }

        const int done = pro + (n4 << 2);
        const int tail = VOCAB - done;
        if (tid < tail) s1 += __expf(p[done + tid]);

        float s = (s0 + s1) + (s2 + s3);

        // Block reduction (fixed order -> deterministic).
        #pragma unroll
        for (int o = 16; o > 0; o >>= 1)
            s += __shfl_xor_sync(0xffffffffu, s, o);
        if (lid == 0) sm[buf][wid] = s;
        __syncthreads();   // single barrier; tid0 finalizes from this buffer
        if (tid == 0) {
            float v = 0.f;
            #pragma unroll
            for (int w = 0; w < 16; w++) v += sm[buf][w];
            const int t = y[row];
            // loss_row = log(sum_j exp(p_j)) - p[y]
            g_row_loss[row] = __logf(v) - p[t];
        }
    }

    // CTA finished all its rows: signal, last CTA reduces.
    __shared__ bool is_last;
    __syncthreads();   // ensure tid0's last g_row_loss store precedes fence
    if (tid == 0) {
        __threadfence();
        unsigned int prev = atomicAdd(&g_done, 1u);
        is_last = (prev == (unsigned)(NBLK - 1));
    }
    __syncthreads();

    if (is_last) {
        float r = 0.f;
        #pragma unroll
        for (int k = 0; k < BATCH / NTHR; k++)
            r += g_row_loss[tid + k * NTHR];

        #pragma unroll
        for (int o = 16; o > 0; o >>= 1)
            r += __shfl_xor_sync(0xffffffffu, r, o);
        if (lid == 0) sm[0][wid] = r;
        __syncthreads();
        if (tid == 0) {
            float tot = 0.f;
            #pragma unroll
            for (int w = 0; w < 16; w++) tot += sm[0][w];
            out[0] = tot * (1.0f / BATCH);
            g_done = 0;   // reset for next launch / graph replay
        }
    }
}

extern "C" void kernel_launch(void* const* d_in, const int* in_sizes, int n_in,
                              void* d_out, int out_size)
{
    const float* pred = (const float*)d_in[0];
    const int* y = (const int*)d_in[1];
    float* out = (float*)d_out;

    ce_fused_kernel<<<NBLK, NTHR>>>(pred, y, out);
}